// round 10
// baseline (speedup 1.0000x reference)
#include <cuda_runtime.h>
#include <cstdint>

#define C_  512
#define Hh  24
#define Ww  24
#define HW  576
#define NH  8
#define HD  64
#define PW  30
#define PP  900
#define KP  960
#define SEW 964            /* sE row stride: 4 mod 32 -> conflict-free frag reads */

typedef unsigned long long ull;

// Scratch (device globals: allocation-free)
__device__ float g_QT[HW * C_];   // Q transposed: [p][o]
__device__ float g_KT[KP * C_];   // K transposed: [pp][o]
__device__ float g_V [C_ * KP];   // V: [o][pp]

// ---- tf32 tensor-core helpers ----
__device__ __forceinline__ uint32_t f2tf(float f) {
    uint32_t r; asm("cvt.rna.tf32.f32 %0, %1;" : "=r"(r) : "f"(f)); return r;
}
__device__ __forceinline__ void mma_tf32(float* c, const uint32_t* a, const uint32_t* b) {
    asm("mma.sync.aligned.m16n8k8.row.col.f32.tf32.tf32.f32 "
        "{%0,%1,%2,%3}, {%4,%5,%6,%7}, {%8,%9}, {%0,%1,%2,%3};"
        : "+f"(c[0]), "+f"(c[1]), "+f"(c[2]), "+f"(c[3])
        : "r"(a[0]), "r"(a[1]), "r"(a[2]), "r"(a[3]), "r"(b[0]), "r"(b[1]));
}

// ---------------------------------------------------------------------------
// Kernel 1: three conv1x1 GEMMs via mma.sync tf32 (R6-proven inner loop),
// with the reflect-pad gather INLINED into B staging (pad_kernel removed).
// Each thread's 16 B-columns are fixed -> reflect offsets computed ONCE.
//   bid [0,72)   : QT = (Wq @ x )^T (N=576, transposed store)
//   bid [72,192) : KT = (Wk @ Xp)^T (N=960, Xp gathered on the fly)
//   bid [192,312): V  =  Wv @ Xp    (N=960, direct store)
// CTA tile 64o x 64n, 4 warps (2x2), warp tile 32x32. k-chunk 32, dbl-buffer.
// ---------------------------------------------------------------------------
__global__ void __launch_bounds__(128) gemm_all_kernel(
    const float* __restrict__ Wq, const float* __restrict__ bq,
    const float* __restrict__ Wk, const float* __restrict__ bk,
    const float* __restrict__ Wv, const float* __restrict__ bv,
    const float* __restrict__ x)
{
    __shared__ uint32_t smu[9216];   // sA0[2304] sA1[2304] sB0[2304] sB1[2304] = 36KB
    uint32_t* sA[2] = { smu,        smu + 2304 };   // [o][k] tf32, stride 36
    uint32_t* sB[2] = { smu + 4608, smu + 6912 };   // [k][n] tf32, stride 72

    int bid = blockIdx.x;
    const float *Wm, *bias; float* Cout; int N, transp, padded, nt, ot;
    if (bid < 72)       { nt = bid % 9;      ot = bid / 9;       Wm = Wq; bias = bq; Cout = g_QT; N = HW; transp = 1; padded = 0; }
    else if (bid < 192) { int b = bid - 72;  nt = b % 15; ot = b / 15; Wm = Wk; bias = bk; Cout = g_KT; N = KP; transp = 1; padded = 1; }
    else                { int b = bid - 192; nt = b % 15; ot = b / 15; Wm = Wv; bias = bv; Cout = g_V;  N = KP; transp = 0; padded = 1; }
    int nB = nt * 64, oB = ot * 64;

    int tid  = threadIdx.x;
    int lane = tid & 31, wid = tid >> 5;
    int warp_m = wid & 1, warp_n = wid >> 1;     // 2x2 warps
    int grp = lane >> 2, qd = lane & 3;

    int arow = tid >> 1, ahalf = (tid & 1) << 4;     // A: 64 rows x 2 halves of 16
    int brow = tid >> 2, boff  = (tid & 3) << 4;     // B: 32 rows x 4 groups of 16

    // ---- one-time reflect-pad offset table for this thread's 16 B-columns ----
    int xoff[16];
#pragma unroll
    for (int e = 0; e < 16; e++) {
        int n = nB + boff + e;
        if (!padded) {
            xoff[e] = n;                         // Q: direct pixel index (<576)
        } else if (n < PP) {
            int pr = n / PW, pc = n - pr * PW;
            int r = pr - 3;  r  = (r  < 0) ? -r  : ((r  >= Hh) ? 2 * Hh - 2 - r  : r );
            int cl = pc - 3; cl = (cl < 0) ? -cl : ((cl >= Ww) ? 2 * Ww - 2 - cl : cl);
            xoff[e] = r * Ww + cl;
        } else {
            xoff[e] = -1;                        // padded key: contributes 0
        }
    }

    float acc[2][4][4];
#pragma unroll
    for (int i = 0; i < 2; i++)
#pragma unroll
        for (int j = 0; j < 4; j++)
#pragma unroll
            for (int e = 0; e < 4; e++) acc[i][j][e] = 0.f;

    // stage chunk 0
    {
        const float4* aS = (const float4*)&Wm[(oB + arow) * C_ + ahalf];
        const float* xrow = &x[brow * HW];
#pragma unroll
        for (int g = 0; g < 4; g++) {
            float4 w = aS[g];
            uint4 t = make_uint4(f2tf(w.x), f2tf(w.y), f2tf(w.z), f2tf(w.w));
            *(uint4*)&sA[0][arow * 36 + ahalf + 4 * g] = t;
        }
        float xv[16];
#pragma unroll
        for (int e = 0; e < 16; e++)
            xv[e] = (xoff[e] >= 0) ? xrow[xoff[e]] : 0.f;
#pragma unroll
        for (int g = 0; g < 4; g++) {
            uint4 t = make_uint4(f2tf(xv[4*g]), f2tf(xv[4*g+1]), f2tf(xv[4*g+2]), f2tf(xv[4*g+3]));
            *(uint4*)&sB[0][brow * 72 + boff + 4 * g] = t;
        }
    }
    __syncthreads();

    int buf = 0;
    for (int cc = 0; cc < C_; cc += 32) {
        bool pf = cc + 32 < C_;
        float4 wreg[4];
        float xv[16];
        if (pf) {
            const float4* aS = (const float4*)&Wm[(oB + arow) * C_ + cc + 32 + ahalf];
#pragma unroll
            for (int g = 0; g < 4; g++) wreg[g] = aS[g];
            const float* xrow = &x[(cc + 32 + brow) * HW];
#pragma unroll
            for (int e = 0; e < 16; e++)
                xv[e] = (xoff[e] >= 0) ? xrow[xoff[e]] : 0.f;
        }
        const uint32_t* cA = sA[buf];
        const uint32_t* cB = sB[buf];
#pragma unroll
        for (int ks = 0; ks < 4; ks++) {
            int kb = ks << 3;
            uint32_t afr[2][4];
#pragma unroll
            for (int ms = 0; ms < 2; ms++) {
                int base = warp_m * 32 + ms * 16 + grp;
                afr[ms][0] = cA[(base    ) * 36 + kb + qd];
                afr[ms][1] = cA[(base + 8) * 36 + kb + qd];
                afr[ms][2] = cA[(base    ) * 36 + kb + 4 + qd];
                afr[ms][3] = cA[(base + 8) * 36 + kb + 4 + qd];
            }
            uint32_t bfr[4][2];
#pragma unroll
            for (int ns = 0; ns < 4; ns++) {
                int n = warp_n * 32 + ns * 8 + grp;
                bfr[ns][0] = cB[(kb + qd    ) * 72 + n];
                bfr[ns][1] = cB[(kb + 4 + qd) * 72 + n];
            }
#pragma unroll
            for (int ms = 0; ms < 2; ms++)
#pragma unroll
                for (int ns = 0; ns < 4; ns++)
                    mma_tf32(acc[ms][ns], afr[ms], bfr[ns]);
        }
        if (pf) {
            uint32_t* nA = sA[buf ^ 1];
            uint32_t* nBp = sB[buf ^ 1];
#pragma unroll
            for (int g = 0; g < 4; g++) {
                float4 w = wreg[g];
                uint4 t = make_uint4(f2tf(w.x), f2tf(w.y), f2tf(w.z), f2tf(w.w));
                *(uint4*)&nA[arow * 36 + ahalf + 4 * g] = t;
            }
#pragma unroll
            for (int g = 0; g < 4; g++) {
                uint4 t = make_uint4(f2tf(xv[4*g]), f2tf(xv[4*g+1]), f2tf(xv[4*g+2]), f2tf(xv[4*g+3]));
                *(uint4*)&nBp[brow * 72 + boff + 4 * g] = t;
            }
        }
        __syncthreads();
        buf ^= 1;
    }

    // epilogue
    if (!transp) {
#pragma unroll
        for (int ms = 0; ms < 2; ms++)
#pragma unroll
            for (int part = 0; part < 2; part++) {
                int row = warp_m * 32 + ms * 16 + grp + part * 8;
                float bv_ = bias[oB + row];
#pragma unroll
                for (int ns = 0; ns < 4; ns++) {
                    float2 val = make_float2(acc[ms][ns][2 * part] + bv_,
                                             acc[ms][ns][2 * part + 1] + bv_);
                    *(float2*)&Cout[(oB + row) * N + nB + warp_n * 32 + ns * 8 + 2 * qd] = val;
                }
            }
    } else {
        float* sT = (float*)smu;                 // [n][o], 64 x 65 = 4160 <= 9216
#pragma unroll
        for (int ms = 0; ms < 2; ms++)
#pragma unroll
            for (int part = 0; part < 2; part++) {
                int row = warp_m * 32 + ms * 16 + grp + part * 8;
                float bv_ = bias[oB + row];
#pragma unroll
                for (int ns = 0; ns < 4; ns++) {
                    int n = warp_n * 32 + ns * 8 + 2 * qd;
                    sT[(n    ) * 65 + row] = acc[ms][ns][2 * part] + bv_;
                    sT[(n + 1) * 65 + row] = acc[ms][ns][2 * part + 1] + bv_;
                }
            }
        __syncthreads();
#pragma unroll
        for (int it = 0; it < 32; it++) {
            int idx = it * 128 + tid;
            int n = idx >> 6, o = idx & 63;
            Cout[(nB + n) * C_ + oB + o] = sT[n * 65 + o];
        }
    }
}

// ---------------------------------------------------------------------------
// Kernel 2: fused attention via mma.sync tf32. Grid (18,8) = 144 CTAs x 256.
// (R8 verbatim — proven)
// ---------------------------------------------------------------------------
__global__ void __launch_bounds__(256) attn_kernel(const float* __restrict__ x,
                            const float* __restrict__ gamma_p,
                            float* __restrict__ out) {
    extern __shared__ float smd[];
    uint32_t* sQf = (uint32_t*)smd;        // 2048: A-frags [ms 2][ks 8][lane 32][4]
    float* sKV0 = smd + 2048;              // 64*68 = 4352 (tf32 bits)
    float* sKV1 = sKV0 + 4352;             // 4352
    float* sE   = sKV1 + 4352;             // 32*964 = 30848
    float* sInv = sE + 32 * SEW;           // 32

    int h   = blockIdx.y;
    int q0  = blockIdx.x * 32;
    int tid = threadIdx.x;
    int w = tid >> 5, lane = tid & 31, grp = lane >> 2, qd = lane & 3;
    int dstg = tid >> 2, cstg = (tid & 3) << 4;
    float* sKVb[2] = { sKV0, sKV1 };

    // ---- Stage Q fragments (one-time) ----
    {
        int q = tid >> 3, db = (tid & 7) << 3;
        float4 qa = *(const float4*)&g_QT[(q0 + q) * C_ + h * HD + db];
        float4 qb = *(const float4*)&g_QT[(q0 + q) * C_ + h * HD + db + 4];
        int ms = q >> 4, qg = q & 7, hi = (q >> 3) & 1;
        float qv[8] = {qa.x, qa.y, qa.z, qa.w, qb.x, qb.y, qb.z, qb.w};
#pragma unroll
        for (int e = 0; e < 8; e++) {
            int d = db + e;
            sQf[((ms * 8 + (d >> 3)) * 32 + (qg << 2) + (d & 3)) * 4 + hi + (((d >> 2) & 1) << 1)] = f2tf(qv[e]);
        }
    }
    // ---- preload K chunk 0 ----
    {
        const float4* src = (const float4*)&g_KT[dstg * C_ + h * HD + cstg];
        uint32_t* dst = (uint32_t*)&sKV0[dstg * 68 + cstg];
#pragma unroll
        for (int j = 0; j < 4; j++) {
            float4 r = src[j];
            *(uint4*)&dst[4 * j] = make_uint4(f2tf(r.x), f2tf(r.y), f2tf(r.z), f2tf(r.w));
        }
    }
    __syncthreads();

    // ---- Pass 1: E = Q^T K ----
    for (int kc = 0, c = 0; kc < KP; kc += 64, c++) {
        const uint32_t* cK = (const uint32_t*)sKVb[c & 1];
        bool pf = kc + 64 < KP;
        float4 r0, r1, r2, r3;
        if (pf) {
            const float4* src = (const float4*)&g_KT[(kc + 64 + dstg) * C_ + h * HD + cstg];
            r0 = src[0]; r1 = src[1]; r2 = src[2]; r3 = src[3];
        }
        float acc0[4] = {0.f, 0.f, 0.f, 0.f};
        float acc1[4] = {0.f, 0.f, 0.f, 0.f};
#pragma unroll
        for (int ks = 0; ks < 8; ks++) {
            uint4 a0 = *(const uint4*)&sQf[((    ks) * 32 + lane) * 4];
            uint4 a1 = *(const uint4*)&sQf[((8 + ks) * 32 + lane) * 4];
            uint32_t bf[2];
            bf[0] = cK[(w * 8 + grp) * 68 + ks * 8 + qd];
            bf[1] = cK[(w * 8 + grp) * 68 + ks * 8 + 4 + qd];
            mma_tf32(acc0, (const uint32_t*)&a0, bf);
            mma_tf32(acc1, (const uint32_t*)&a1, bf);
        }
        {
            int col = kc + w * 8 + 2 * qd;
            *(float2*)&sE[(grp     ) * SEW + col] = make_float2(acc0[0], acc0[1]);
            *(float2*)&sE[(grp +  8) * SEW + col] = make_float2(acc0[2], acc0[3]);
            *(float2*)&sE[(grp + 16) * SEW + col] = make_float2(acc1[0], acc1[1]);
            *(float2*)&sE[(grp + 24) * SEW + col] = make_float2(acc1[2], acc1[3]);
        }
        if (pf) {
            uint32_t* dst = (uint32_t*)&sKVb[(c & 1) ^ 1][dstg * 68 + cstg];
            *(uint4*)&dst[0]  = make_uint4(f2tf(r0.x), f2tf(r0.y), f2tf(r0.z), f2tf(r0.w));
            *(uint4*)&dst[4]  = make_uint4(f2tf(r1.x), f2tf(r1.y), f2tf(r1.z), f2tf(r1.w));
            *(uint4*)&dst[8]  = make_uint4(f2tf(r2.x), f2tf(r2.y), f2tf(r2.z), f2tf(r2.w));
            *(uint4*)&dst[12] = make_uint4(f2tf(r3.x), f2tf(r3.y), f2tf(r3.z), f2tf(r3.w));
        }
        __syncthreads();
    }

    // ---- prefetch V chunk 0 ----
    float4 v0r, v1r, v2r, v3r;
    {
        const float4* src = (const float4*)&g_V[(h * HD + dstg) * KP + cstg];
        v0r = src[0]; v1r = src[1]; v2r = src[2]; v3r = src[3];
    }

    // ---- Multiplicity-weighted softmax; tf32-rounded P in place ----
    {
        int row = tid >> 3, part = tid & 7;
        float* Er = &sE[row * SEW];
        int i0 = part * 120;
        float m = -1e30f;
        for (int i = i0; i < i0 + 120; i++) m = fmaxf(m, Er[i]);
        m = fmaxf(m, __shfl_xor_sync(~0u, m, 1));
        m = fmaxf(m, __shfl_xor_sync(~0u, m, 2));
        m = fmaxf(m, __shfl_xor_sync(~0u, m, 4));
        float s = 0.f;
        for (int i = i0; i < i0 + 120; i++) {
            float wgt = 0.f;
            if (i < PP) {
                int pr = i / PW, pc = i - pr * PW;
                int mr = min(pr + 1, min(7, PW - pr));
                int mc = min(pc + 1, min(7, PW - pc));
                wgt = (float)(mr * mc);
            }
            float p = __uint_as_float(f2tf(wgt * __expf(Er[i] - m)));
            Er[i] = p;
            s += p;
        }
        s += __shfl_xor_sync(~0u, s, 1);
        s += __shfl_xor_sync(~0u, s, 2);
        s += __shfl_xor_sync(~0u, s, 4);
        if (part == 0) sInv[row] = 1.f / s;
    }
    {
        uint32_t* dst = (uint32_t*)&sKV0[dstg * 68 + cstg];
        *(uint4*)&dst[0]  = make_uint4(f2tf(v0r.x), f2tf(v0r.y), f2tf(v0r.z), f2tf(v0r.w));
        *(uint4*)&dst[4]  = make_uint4(f2tf(v1r.x), f2tf(v1r.y), f2tf(v1r.z), f2tf(v1r.w));
        *(uint4*)&dst[8]  = make_uint4(f2tf(v2r.x), f2tf(v2r.y), f2tf(v2r.z), f2tf(v2r.w));
        *(uint4*)&dst[12] = make_uint4(f2tf(v3r.x), f2tf(v3r.y), f2tf(v3r.z), f2tf(v3r.w));
    }
    __syncthreads();

    // ---- Pass 2: out = P V ----
    float o0[4] = {0.f, 0.f, 0.f, 0.f};
    float o1[4] = {0.f, 0.f, 0.f, 0.f};
    for (int kc = 0, c = 0; kc < KP; kc += 64, c++) {
        const uint32_t* cV = (const uint32_t*)sKVb[c & 1];
        bool pf = kc + 64 < KP;
        float4 r0, r1, r2, r3;
        if (pf) {
            const float4* src = (const float4*)&g_V[(h * HD + dstg) * KP + kc + 64 + cstg];
            r0 = src[0]; r1 = src[1]; r2 = src[2]; r3 = src[3];
        }
#pragma unroll
        for (int ks = 0; ks < 8; ks++) {
            int colb = kc + ks * 8;
            uint32_t a0[4], a1[4], bf[2];
            a0[0] = __float_as_uint(sE[(grp     ) * SEW + colb + qd]);
            a0[1] = __float_as_uint(sE[(grp +  8) * SEW + colb + qd]);
            a0[2] = __float_as_uint(sE[(grp     ) * SEW + colb + 4 + qd]);
            a0[3] = __float_as_uint(sE[(grp +  8) * SEW + colb + 4 + qd]);
            a1[0] = __float_as_uint(sE[(grp + 16) * SEW + colb + qd]);
            a1[1] = __float_as_uint(sE[(grp + 24) * SEW + colb + qd]);
            a1[2] = __float_as_uint(sE[(grp + 16) * SEW + colb + 4 + qd]);
            a1[3] = __float_as_uint(sE[(grp + 24) * SEW + colb + 4 + qd]);
            bf[0] = cV[(w * 8 + grp) * 68 + ks * 8 + qd];
            bf[1] = cV[(w * 8 + grp) * 68 + ks * 8 + 4 + qd];
            mma_tf32(o0, a0, bf);
            mma_tf32(o1, a1, bf);
        }
        if (pf) {
            uint32_t* dst = (uint32_t*)&sKVb[(c & 1) ^ 1][dstg * 68 + cstg];
            *(uint4*)&dst[0]  = make_uint4(f2tf(r0.x), f2tf(r0.y), f2tf(r0.z), f2tf(r0.w));
            *(uint4*)&dst[4]  = make_uint4(f2tf(r1.x), f2tf(r1.y), f2tf(r1.z), f2tf(r1.w));
            *(uint4*)&dst[8]  = make_uint4(f2tf(r2.x), f2tf(r2.y), f2tf(r2.z), f2tf(r2.w));
            *(uint4*)&dst[12] = make_uint4(f2tf(r3.x), f2tf(r3.y), f2tf(r3.z), f2tf(r3.w));
        }
        __syncthreads();
    }

    // ---- Epilogue via smem transpose ----
    {
        float* sT = sKV0;                        // [d][q] 64 x 33 = 2112
        int dc = w * 8 + 2 * qd;
        sT[(dc    ) * 33 + grp     ] = o0[0];
        sT[(dc + 1) * 33 + grp     ] = o0[1];
        sT[(dc    ) * 33 + grp +  8] = o0[2];
        sT[(dc + 1) * 33 + grp +  8] = o0[3];
        sT[(dc    ) * 33 + grp + 16] = o1[0];
        sT[(dc + 1) * 33 + grp + 16] = o1[1];
        sT[(dc    ) * 33 + grp + 24] = o1[2];
        sT[(dc + 1) * 33 + grp + 24] = o1[3];
        __syncthreads();
        float g = *gamma_p;
        for (int i = tid; i < 64 * 32; i += 256) {
            int d = i >> 5, q = i & 31;
            int gi = (h * HD + d) * HW + q0 + q;
            out[gi] = g * sT[d * 33 + q] * sInv[q] + x[gi];
        }
    }
}

// ---------------------------------------------------------------------------
extern "C" void kernel_launch(void* const* d_in, const int* in_sizes, int n_in,
                              void* d_out, int out_size) {
    const float* x     = (const float*)d_in[0];
    const float* Wq    = (const float*)d_in[1];
    const float* bq    = (const float*)d_in[2];
    const float* Wk    = (const float*)d_in[3];
    const float* bk    = (const float*)d_in[4];
    const float* Wv    = (const float*)d_in[5];
    const float* bv    = (const float*)d_in[6];
    const float* gamma = (const float*)d_in[7];
    float* out = (float*)d_out;

    gemm_all_kernel<<<312, 128>>>(Wq, bq, Wk, bk, Wv, bv, x);

    const int smem_bytes = (2048 + 2 * 4352 + 32 * SEW + 32) * 4;  // 166528
    cudaFuncSetAttribute(attn_kernel, cudaFuncAttributeMaxDynamicSharedMemorySize, smem_bytes);
    attn_kernel<<<dim3(HW / 32, NH), 256, smem_bytes>>>(x, gamma, out);
}

// round 11
// speedup vs baseline: 1.0922x; 1.0922x over previous
#include <cuda_runtime.h>
#include <cstdint>

#define C_  512
#define Hh  24
#define Ww  24
#define HW  576
#define NH  8
#define HD  64
#define PW  30
#define PP  900
#define KP  960
#define SEW 964            /* sE row stride: 4 mod 32 -> conflict-free frag reads */

typedef unsigned long long ull;

// Scratch (device globals: allocation-free)
__device__ float g_Xp[C_ * KP];   // reflect-padded x, keys padded to 960 (zeros)
__device__ float g_QT[HW * C_];   // Q transposed: [p][o]
__device__ float g_KT[KP * C_];   // K transposed: [pp][o]
__device__ float g_V [C_ * KP];   // V: [o][pp]

// ---- tf32 tensor-core helpers ----
__device__ __forceinline__ uint32_t f2tf(float f) {
    uint32_t r; asm("cvt.rna.tf32.f32 %0, %1;" : "=r"(r) : "f"(f)); return r;
}
__device__ __forceinline__ void mma_tf32(float* c, const uint32_t* a, const uint32_t* b) {
    asm("mma.sync.aligned.m16n8k8.row.col.f32.tf32.tf32.f32 "
        "{%0,%1,%2,%3}, {%4,%5,%6,%7}, {%8,%9}, {%0,%1,%2,%3};"
        : "+f"(c[0]), "+f"(c[1]), "+f"(c[2]), "+f"(c[3])
        : "r"(a[0]), "r"(a[1]), "r"(a[2]), "r"(a[3]), "r"(b[0]), "r"(b[1]));
}

// ---------------------------------------------------------------------------
// Kernel 1: reflect-pad gather. g_Xp[c][pp] (pp = pr*30+pc), zeros for pp>=900.
// ---------------------------------------------------------------------------
__global__ void pad_kernel(const float* __restrict__ x) {
    int idx = blockIdx.x * 256 + threadIdx.x;
    if (idx >= C_ * KP) return;
    int c = idx / KP, pp = idx - c * KP;
    float v = 0.f;
    if (pp < PP) {
        int pr = pp / PW, pc = pp - pr * PW;
        int r = pr - 3; r = (r < 0) ? -r : ((r >= Hh) ? 2 * Hh - 2 - r : r);
        int cl = pc - 3; cl = (cl < 0) ? -cl : ((cl >= Ww) ? 2 * Ww - 2 - cl : cl);
        v = x[c * HW + r * Ww + cl];
    }
    g_Xp[idx] = v;
}

// ---------------------------------------------------------------------------
// Kernel 2: three conv1x1 GEMMs via mma.sync tf32, DUAL-TILE CTAs.
// 256 threads = two 128-thread groups; group g computes output tile
// oB=(otp*2+g)*64 over the SAME B tile (staged once, shared). Grid = 156
// CTAs = one wave; 8 warps/CTA. Inner loop = R6-proven body per group.
//   bid [0,36)  : QT = (Wq @ x )^T (N=576, transposed store)
//   bid [36,96) : KT = (Wk @ Xp)^T (N=960, transposed store)
//   bid [96,156): V  =  Wv @ Xp    (N=960, direct store)
// ---------------------------------------------------------------------------
__global__ void __launch_bounds__(256) gemm_all_kernel(
    const float* __restrict__ Wq, const float* __restrict__ bq,
    const float* __restrict__ Wk, const float* __restrict__ bk,
    const float* __restrict__ Wv, const float* __restrict__ bv,
    const float* __restrict__ x)
{
    extern __shared__ uint32_t smu[];
    // layout (u32): sB0@0[2304] sB1@2304[2304] | g0: sA0@4608 sA1@6912 | g1: sA0@9216 sA1@11520
    // total 13824 u32 = 55296 B

    int bid = blockIdx.x;
    const float *Wm, *bias, *X; float* Cout; int N, transp, nt, otp;
    if (bid < 36)      { nt = bid % 9;      otp = bid / 9;       Wm = Wq; bias = bq; X = x;    Cout = g_QT; N = HW; transp = 1; }
    else if (bid < 96) { int b = bid - 36;  nt = b % 15; otp = b / 15; Wm = Wk; bias = bk; X = g_Xp; Cout = g_KT; N = KP; transp = 1; }
    else               { int b = bid - 96;  nt = b % 15; otp = b / 15; Wm = Wv; bias = bv; X = g_Xp; Cout = g_V;  N = KP; transp = 0; }

    int tid  = threadIdx.x;
    int g    = tid >> 7, ltid = tid & 127;
    int nB = nt * 64, oB = (otp * 2 + g) * 64;

    int lane = ltid & 31, wid = ltid >> 5;
    int warp_m = wid & 1, warp_n = wid >> 1;         // 2x2 warps per group
    int grp = lane >> 2, qd = lane & 3;

    int arow = ltid >> 1, ahalf = (ltid & 1) << 4;   // A: 64 rows x 2 halves of 16 (per group)
    int brow = tid >> 3, boff  = (tid & 7) << 3;     // B: 32 rows x 8 groups of 8 (all 256 thr)

    uint32_t* sB[2] = { smu,                  smu + 2304 };            // [k][n], stride 72
    uint32_t* sA[2] = { smu + 4608 + g * 4608, smu + 6912 + g * 4608 }; // [o][k], stride 36

    float acc[2][4][4];
#pragma unroll
    for (int i = 0; i < 2; i++)
#pragma unroll
        for (int j = 0; j < 4; j++)
#pragma unroll
            for (int e = 0; e < 4; e++) acc[i][j][e] = 0.f;

    // stage chunk 0
    {
        const float4* aS = (const float4*)&Wm[(oB + arow) * C_ + ahalf];
#pragma unroll
        for (int gg = 0; gg < 4; gg++) {
            float4 w = aS[gg];
            uint4 t = make_uint4(f2tf(w.x), f2tf(w.y), f2tf(w.z), f2tf(w.w));
            *(uint4*)&sA[0][arow * 36 + ahalf + 4 * gg] = t;
        }
        const float4* bS = (const float4*)&X[brow * N + nB + boff];
#pragma unroll
        for (int gg = 0; gg < 2; gg++) {
            float4 v = bS[gg];
            uint4 t = make_uint4(f2tf(v.x), f2tf(v.y), f2tf(v.z), f2tf(v.w));
            *(uint4*)&sB[0][brow * 72 + boff + 4 * gg] = t;
        }
    }
    __syncthreads();

    int buf = 0;
    for (int cc = 0; cc < C_; cc += 32) {
        bool pf = cc + 32 < C_;
        float4 wreg[4], xreg[2];
        if (pf) {
            const float4* aS = (const float4*)&Wm[(oB + arow) * C_ + cc + 32 + ahalf];
#pragma unroll
            for (int gg = 0; gg < 4; gg++) wreg[gg] = aS[gg];
            const float4* bS = (const float4*)&X[(cc + 32 + brow) * N + nB + boff];
            xreg[0] = bS[0]; xreg[1] = bS[1];
        }
        const uint32_t* cA = sA[buf];
        const uint32_t* cB = sB[buf];
#pragma unroll
        for (int ks = 0; ks < 4; ks++) {
            int kb = ks << 3;
            uint32_t afr[2][4];
#pragma unroll
            for (int ms = 0; ms < 2; ms++) {
                int base = warp_m * 32 + ms * 16 + grp;
                afr[ms][0] = cA[(base    ) * 36 + kb + qd];
                afr[ms][1] = cA[(base + 8) * 36 + kb + qd];
                afr[ms][2] = cA[(base    ) * 36 + kb + 4 + qd];
                afr[ms][3] = cA[(base + 8) * 36 + kb + 4 + qd];
            }
            uint32_t bfr[4][2];
#pragma unroll
            for (int ns = 0; ns < 4; ns++) {
                int n = warp_n * 32 + ns * 8 + grp;
                bfr[ns][0] = cB[(kb + qd    ) * 72 + n];
                bfr[ns][1] = cB[(kb + 4 + qd) * 72 + n];
            }
#pragma unroll
            for (int ms = 0; ms < 2; ms++)
#pragma unroll
                for (int ns = 0; ns < 4; ns++)
                    mma_tf32(acc[ms][ns], afr[ms], bfr[ns]);
        }
        if (pf) {
            uint32_t* nA = sA[buf ^ 1];
            uint32_t* nBp = sB[buf ^ 1];
#pragma unroll
            for (int gg = 0; gg < 4; gg++) {
                float4 w = wreg[gg];
                uint4 t = make_uint4(f2tf(w.x), f2tf(w.y), f2tf(w.z), f2tf(w.w));
                *(uint4*)&nA[arow * 36 + ahalf + 4 * gg] = t;
            }
#pragma unroll
            for (int gg = 0; gg < 2; gg++) {
                float4 v = xreg[gg];
                uint4 t = make_uint4(f2tf(v.x), f2tf(v.y), f2tf(v.z), f2tf(v.w));
                *(uint4*)&sB[buf ^ 1][0] , (void)0;   // no-op guard (kept simple below)
                *(uint4*)&nBp[brow * 72 + boff + 4 * gg] = t;
            }
        }
        __syncthreads();
        buf ^= 1;
    }

    // ---- epilogue (per group; R6-proven) ----
    if (!transp) {
#pragma unroll
        for (int ms = 0; ms < 2; ms++)
#pragma unroll
            for (int part = 0; part < 2; part++) {
                int row = warp_m * 32 + ms * 16 + grp + part * 8;
                float bv_ = bias[oB + row];
#pragma unroll
                for (int ns = 0; ns < 4; ns++) {
                    float2 val = make_float2(acc[ms][ns][2 * part] + bv_,
                                             acc[ms][ns][2 * part + 1] + bv_);
                    *(float2*)&Cout[(oB + row) * N + nB + warp_n * 32 + ns * 8 + 2 * qd] = val;
                }
            }
    } else {
        float* sT = (float*)smu + g * 4224;      // [n][o], 64 x 65 per group (8448 <= 13824)
#pragma unroll
        for (int ms = 0; ms < 2; ms++)
#pragma unroll
            for (int part = 0; part < 2; part++) {
                int row = warp_m * 32 + ms * 16 + grp + part * 8;
                float bv_ = bias[oB + row];
#pragma unroll
                for (int ns = 0; ns < 4; ns++) {
                    int n = warp_n * 32 + ns * 8 + 2 * qd;
                    sT[(n    ) * 65 + row] = acc[ms][ns][2 * part] + bv_;
                    sT[(n + 1) * 65 + row] = acc[ms][ns][2 * part + 1] + bv_;
                }
            }
        __syncthreads();
#pragma unroll
        for (int it = 0; it < 32; it++) {
            int idx = it * 128 + ltid;
            int n = idx >> 6, o = idx & 63;
            Cout[(nB + n) * C_ + oB + o] = sT[n * 65 + o];
        }
    }
}

// ---------------------------------------------------------------------------
// Kernel 3: fused attention via mma.sync tf32. Grid (18,8) = 144 CTAs x 256.
// (R8 verbatim — proven)
// ---------------------------------------------------------------------------
__global__ void __launch_bounds__(256) attn_kernel(const float* __restrict__ x,
                            const float* __restrict__ gamma_p,
                            float* __restrict__ out) {
    extern __shared__ float smd[];
    uint32_t* sQf = (uint32_t*)smd;        // 2048: A-frags [ms 2][ks 8][lane 32][4]
    float* sKV0 = smd + 2048;              // 64*68 = 4352 (tf32 bits)
    float* sKV1 = sKV0 + 4352;             // 4352
    float* sE   = sKV1 + 4352;             // 32*964 = 30848
    float* sInv = sE + 32 * SEW;           // 32

    int h   = blockIdx.y;
    int q0  = blockIdx.x * 32;
    int tid = threadIdx.x;
    int w = tid >> 5, lane = tid & 31, grp = lane >> 2, qd = lane & 3;
    int dstg = tid >> 2, cstg = (tid & 3) << 4;
    float* sKVb[2] = { sKV0, sKV1 };

    // ---- Stage Q fragments (one-time) ----
    {
        int q = tid >> 3, db = (tid & 7) << 3;
        float4 qa = *(const float4*)&g_QT[(q0 + q) * C_ + h * HD + db];
        float4 qb = *(const float4*)&g_QT[(q0 + q) * C_ + h * HD + db + 4];
        int ms = q >> 4, qg = q & 7, hi = (q >> 3) & 1;
        float qv[8] = {qa.x, qa.y, qa.z, qa.w, qb.x, qb.y, qb.z, qb.w};
#pragma unroll
        for (int e = 0; e < 8; e++) {
            int d = db + e;
            sQf[((ms * 8 + (d >> 3)) * 32 + (qg << 2) + (d & 3)) * 4 + hi + (((d >> 2) & 1) << 1)] = f2tf(qv[e]);
        }
    }
    // ---- preload K chunk 0 ----
    {
        const float4* src = (const float4*)&g_KT[dstg * C_ + h * HD + cstg];
        uint32_t* dst = (uint32_t*)&sKV0[dstg * 68 + cstg];
#pragma unroll
        for (int j = 0; j < 4; j++) {
            float4 r = src[j];
            *(uint4*)&dst[4 * j] = make_uint4(f2tf(r.x), f2tf(r.y), f2tf(r.z), f2tf(r.w));
        }
    }
    __syncthreads();

    // ---- Pass 1: E = Q^T K ----
    for (int kc = 0, c = 0; kc < KP; kc += 64, c++) {
        const uint32_t* cK = (const uint32_t*)sKVb[c & 1];
        bool pf = kc + 64 < KP;
        float4 r0, r1, r2, r3;
        if (pf) {
            const float4* src = (const float4*)&g_KT[(kc + 64 + dstg) * C_ + h * HD + cstg];
            r0 = src[0]; r1 = src[1]; r2 = src[2]; r3 = src[3];
        }
        float acc0[4] = {0.f, 0.f, 0.f, 0.f};
        float acc1[4] = {0.f, 0.f, 0.f, 0.f};
#pragma unroll
        for (int ks = 0; ks < 8; ks++) {
            uint4 a0 = *(const uint4*)&sQf[((    ks) * 32 + lane) * 4];
            uint4 a1 = *(const uint4*)&sQf[((8 + ks) * 32 + lane) * 4];
            uint32_t bf[2];
            bf[0] = cK[(w * 8 + grp) * 68 + ks * 8 + qd];
            bf[1] = cK[(w * 8 + grp) * 68 + ks * 8 + 4 + qd];
            mma_tf32(acc0, (const uint32_t*)&a0, bf);
            mma_tf32(acc1, (const uint32_t*)&a1, bf);
        }
        {
            int col = kc + w * 8 + 2 * qd;
            *(float2*)&sE[(grp     ) * SEW + col] = make_float2(acc0[0], acc0[1]);
            *(float2*)&sE[(grp +  8) * SEW + col] = make_float2(acc0[2], acc0[3]);
            *(float2*)&sE[(grp + 16) * SEW + col] = make_float2(acc1[0], acc1[1]);
            *(float2*)&sE[(grp + 24) * SEW + col] = make_float2(acc1[2], acc1[3]);
        }
        if (pf) {
            uint32_t* dst = (uint32_t*)&sKVb[(c & 1) ^ 1][dstg * 68 + cstg];
            *(uint4*)&dst[0]  = make_uint4(f2tf(r0.x), f2tf(r0.y), f2tf(r0.z), f2tf(r0.w));
            *(uint4*)&dst[4]  = make_uint4(f2tf(r1.x), f2tf(r1.y), f2tf(r1.z), f2tf(r1.w));
            *(uint4*)&dst[8]  = make_uint4(f2tf(r2.x), f2tf(r2.y), f2tf(r2.z), f2tf(r2.w));
            *(uint4*)&dst[12] = make_uint4(f2tf(r3.x), f2tf(r3.y), f2tf(r3.z), f2tf(r3.w));
        }
        __syncthreads();
    }

    // ---- prefetch V chunk 0 ----
    float4 v0r, v1r, v2r, v3r;
    {
        const float4* src = (const float4*)&g_V[(h * HD + dstg) * KP + cstg];
        v0r = src[0]; v1r = src[1]; v2r = src[2]; v3r = src[3];
    }

    // ---- Multiplicity-weighted softmax; tf32-rounded P in place ----
    {
        int row = tid >> 3, part = tid & 7;
        float* Er = &sE[row * SEW];
        int i0 = part * 120;
        float m = -1e30f;
        for (int i = i0; i < i0 + 120; i++) m = fmaxf(m, Er[i]);
        m = fmaxf(m, __shfl_xor_sync(~0u, m, 1));
        m = fmaxf(m, __shfl_xor_sync(~0u, m, 2));
        m = fmaxf(m, __shfl_xor_sync(~0u, m, 4));
        float s = 0.f;
        for (int i = i0; i < i0 + 120; i++) {
            float wgt = 0.f;
            if (i < PP) {
                int pr = i / PW, pc = i - pr * PW;
                int mr = min(pr + 1, min(7, PW - pr));
                int mc = min(pc + 1, min(7, PW - pc));
                wgt = (float)(mr * mc);
            }
            float p = __uint_as_float(f2tf(wgt * __expf(Er[i] - m)));
            Er[i] = p;
            s += p;
        }
        s += __shfl_xor_sync(~0u, s, 1);
        s += __shfl_xor_sync(~0u, s, 2);
        s += __shfl_xor_sync(~0u, s, 4);
        if (part == 0) sInv[row] = 1.f / s;
    }
    {
        uint32_t* dst = (uint32_t*)&sKV0[dstg * 68 + cstg];
        *(uint4*)&dst[0]  = make_uint4(f2tf(v0r.x), f2tf(v0r.y), f2tf(v0r.z), f2tf(v0r.w));
        *(uint4*)&dst[4]  = make_uint4(f2tf(v1r.x), f2tf(v1r.y), f2tf(v1r.z), f2tf(v1r.w));
        *(uint4*)&dst[8]  = make_uint4(f2tf(v2r.x), f2tf(v2r.y), f2tf(v2r.z), f2tf(v2r.w));
        *(uint4*)&dst[12] = make_uint4(f2tf(v3r.x), f2tf(v3r.y), f2tf(v3r.z), f2tf(v3r.w));
    }
    __syncthreads();

    // ---- Pass 2: out = P V ----
    float o0[4] = {0.f, 0.f, 0.f, 0.f};
    float o1[4] = {0.f, 0.f, 0.f, 0.f};
    for (int kc = 0, c = 0; kc < KP; kc += 64, c++) {
        const uint32_t* cV = (const uint32_t*)sKVb[c & 1];
        bool pf = kc + 64 < KP;
        float4 r0, r1, r2, r3;
        if (pf) {
            const float4* src = (const float4*)&g_V[(h * HD + dstg) * KP + kc + 64 + cstg];
            r0 = src[0]; r1 = src[1]; r2 = src[2]; r3 = src[3];
        }
#pragma unroll
        for (int ks = 0; ks < 8; ks++) {
            int colb = kc + ks * 8;
            uint32_t a0[4], a1[4], bf[2];
            a0[0] = __float_as_uint(sE[(grp     ) * SEW + colb + qd]);
            a0[1] = __float_as_uint(sE[(grp +  8) * SEW + colb + qd]);
            a0[2] = __float_as_uint(sE[(grp     ) * SEW + colb + 4 + qd]);
            a0[3] = __float_as_uint(sE[(grp +  8) * SEW + colb + 4 + qd]);
            a1[0] = __float_as_uint(sE[(grp + 16) * SEW + colb + qd]);
            a1[1] = __float_as_uint(sE[(grp + 24) * SEW + colb + qd]);
            a1[2] = __float_as_uint(sE[(grp + 16) * SEW + colb + 4 + qd]);
            a1[3] = __float_as_uint(sE[(grp + 24) * SEW + colb + 4 + qd]);
            bf[0] = cV[(w * 8 + grp) * 68 + ks * 8 + qd];
            bf[1] = cV[(w * 8 + grp) * 68 + ks * 8 + 4 + qd];
            mma_tf32(o0, a0, bf);
            mma_tf32(o1, a1, bf);
        }
        if (pf) {
            uint32_t* dst = (uint32_t*)&sKVb[(c & 1) ^ 1][dstg * 68 + cstg];
            *(uint4*)&dst[0]  = make_uint4(f2tf(r0.x), f2tf(r0.y), f2tf(r0.z), f2tf(r0.w));
            *(uint4*)&dst[4]  = make_uint4(f2tf(r1.x), f2tf(r1.y), f2tf(r1.z), f2tf(r1.w));
            *(uint4*)&dst[8]  = make_uint4(f2tf(r2.x), f2tf(r2.y), f2tf(r2.z), f2tf(r2.w));
            *(uint4*)&dst[12] = make_uint4(f2tf(r3.x), f2tf(r3.y), f2tf(r3.z), f2tf(r3.w));
        }
        __syncthreads();
    }

    // ---- Epilogue via smem transpose ----
    {
        float* sT = sKV0;                        // [d][q] 64 x 33 = 2112
        int dc = w * 8 + 2 * qd;
        sT[(dc    ) * 33 + grp     ] = o0[0];
        sT[(dc + 1) * 33 + grp     ] = o0[1];
        sT[(dc    ) * 33 + grp +  8] = o0[2];
        sT[(dc + 1) * 33 + grp +  8] = o0[3];
        sT[(dc    ) * 33 + grp + 16] = o1[0];
        sT[(dc + 1) * 33 + grp + 16] = o1[1];
        sT[(dc    ) * 33 + grp + 24] = o1[2];
        sT[(dc + 1) * 33 + grp + 24] = o1[3];
        __syncthreads();
        float g = *gamma_p;
        for (int i = tid; i < 64 * 32; i += 256) {
            int d = i >> 5, q = i & 31;
            int gi = (h * HD + d) * HW + q0 + q;
            out[gi] = g * sT[d * 33 + q] * sInv[q] + x[gi];
        }
    }
}

// ---------------------------------------------------------------------------
extern "C" void kernel_launch(void* const* d_in, const int* in_sizes, int n_in,
                              void* d_out, int out_size) {
    const float* x     = (const float*)d_in[0];
    const float* Wq    = (const float*)d_in[1];
    const float* bq    = (const float*)d_in[2];
    const float* Wk    = (const float*)d_in[3];
    const float* bk    = (const float*)d_in[4];
    const float* Wv    = (const float*)d_in[5];
    const float* bv    = (const float*)d_in[6];
    const float* gamma = (const float*)d_in[7];
    float* out = (float*)d_out;

    pad_kernel<<<(C_ * KP + 255) / 256, 256>>>(x);

    const int gemm_smem = 13824 * 4;   // 55296 B
    cudaFuncSetAttribute(gemm_all_kernel, cudaFuncAttributeMaxDynamicSharedMemorySize, gemm_smem);
    gemm_all_kernel<<<156, 256, gemm_smem>>>(Wq, bq, Wk, bk, Wv, bv, x);

    const int attn_smem = (2048 + 2 * 4352 + 32 * SEW + 32) * 4;  // 166528
    cudaFuncSetAttribute(attn_kernel, cudaFuncAttributeMaxDynamicSharedMemorySize, attn_smem);
    attn_kernel<<<dim3(HW / 32, NH), 256, attn_smem>>>(x, gamma, out);
}

// round 12
// speedup vs baseline: 1.1791x; 1.0796x over previous
#include <cuda_runtime.h>
#include <cstdint>

#define C_  512
#define Hh  24
#define Ww  24
#define HW  576
#define NH  8
#define HD  64
#define PW  30
#define PP  900
#define KP  960
#define SEW 964            /* sE row stride: 4 mod 32 -> conflict-free frag reads */

typedef unsigned long long ull;

// Scratch (device globals: allocation-free)
__device__ float g_Xp[C_ * KP];   // reflect-padded x, keys padded to 960 (zeros)
__device__ float g_QT[HW * C_];   // Q transposed: [p][o]
__device__ float g_KT[KP * C_];   // K transposed: [pp][o]
__device__ float g_V [C_ * KP];   // V: [o][pp]

// ---- tf32 tensor-core helpers ----
__device__ __forceinline__ uint32_t f2tf(float f) {
    uint32_t r; asm("cvt.rna.tf32.f32 %0, %1;" : "=r"(r) : "f"(f)); return r;
}
__device__ __forceinline__ void mma_tf32(float* c, const uint32_t* a, const uint32_t* b) {
    asm("mma.sync.aligned.m16n8k8.row.col.f32.tf32.tf32.f32 "
        "{%0,%1,%2,%3}, {%4,%5,%6,%7}, {%8,%9}, {%0,%1,%2,%3};"
        : "+f"(c[0]), "+f"(c[1]), "+f"(c[2]), "+f"(c[3])
        : "r"(a[0]), "r"(a[1]), "r"(a[2]), "r"(a[3]), "r"(b[0]), "r"(b[1]));
}

// ---- cp.async helpers (zero-register global->shared staging) ----
__device__ __forceinline__ uint32_t s2u(const void* p) {
    return (uint32_t)__cvta_generic_to_shared(p);
}
__device__ __forceinline__ void cp16(uint32_t dst_smem, const void* src) {
    asm volatile("cp.async.ca.shared.global [%0], [%1], 16;"
                 :: "r"(dst_smem), "l"(src));
}
#define CP_COMMIT()  asm volatile("cp.async.commit_group;" ::: "memory")
#define CP_WAIT0()   asm volatile("cp.async.wait_group 0;" ::: "memory")

// ---------------------------------------------------------------------------
// Kernel 1: reflect-pad gather. g_Xp[c][pp] (pp = pr*30+pc), zeros for pp>=900.
// ---------------------------------------------------------------------------
__global__ void pad_kernel(const float* __restrict__ x) {
    int idx = blockIdx.x * 256 + threadIdx.x;
    if (idx >= C_ * KP) return;
    int c = idx / KP, pp = idx - c * KP;
    float v = 0.f;
    if (pp < PP) {
        int pr = pp / PW, pc = pp - pr * PW;
        int r = pr - 3; r = (r < 0) ? -r : ((r >= Hh) ? 2 * Hh - 2 - r : r);
        int cl = pc - 3; cl = (cl < 0) ? -cl : ((cl >= Ww) ? 2 * Ww - 2 - cl : cl);
        v = x[c * HW + r * Ww + cl];
    }
    g_Xp[idx] = v;
}

// ---------------------------------------------------------------------------
// Kernel 2: three conv1x1 GEMMs via mma.sync tf32, cp.async staging.
// Staging is LDGSTS direct to smem (NO prefetch registers, NO cvt — HMMA.TF32
// reads raw fp32 bits, truncating the low mantissa). Inner loop = R6 body.
//   bid [0,72)   : QT = (Wq @ x )^T (N=576, transposed store)
//   bid [72,192) : KT = (Wk @ Xp)^T (N=960, transposed store)
//   bid [192,312): V  =  Wv @ Xp    (N=960, direct store)
// CTA 64x64, 4 warps (2x2), warp tile 32x32. k-chunk 32, double-buffered.
// ---------------------------------------------------------------------------
__global__ void __launch_bounds__(128) gemm_all_kernel(
    const float* __restrict__ Wq, const float* __restrict__ bq,
    const float* __restrict__ Wk, const float* __restrict__ bk,
    const float* __restrict__ Wv, const float* __restrict__ bv,
    const float* __restrict__ x)
{
    __shared__ uint32_t smu[9216];   // sA0[2304] sA1[2304] sB0[2304] sB1[2304] = 36KB
    uint32_t* sA[2] = { smu,        smu + 2304 };   // [o][k] raw fp32, stride 36
    uint32_t* sB[2] = { smu + 4608, smu + 6912 };   // [k][n] raw fp32, stride 72

    int bid = blockIdx.x;
    const float *Wm, *bias, *X; float* Cout; int N, transp, nt, ot;
    if (bid < 72)       { nt = bid % 9;      ot = bid / 9;       Wm = Wq; bias = bq; X = x;    Cout = g_QT; N = HW; transp = 1; }
    else if (bid < 192) { int b = bid - 72;  nt = b % 15; ot = b / 15; Wm = Wk; bias = bk; X = g_Xp; Cout = g_KT; N = KP; transp = 1; }
    else                { int b = bid - 192; nt = b % 15; ot = b / 15; Wm = Wv; bias = bv; X = g_Xp; Cout = g_V;  N = KP; transp = 0; }
    int nB = nt * 64, oB = ot * 64;

    int tid  = threadIdx.x;
    int lane = tid & 31, wid = tid >> 5;
    int warp_m = wid & 1, warp_n = wid >> 1;     // 2x2 warps
    int grp = lane >> 2, qd = lane & 3;

    int arow = tid >> 1, ahalf = (tid & 1) << 4;     // A: 64 rows x 2 halves of 16
    int brow = tid >> 2, boff  = (tid & 3) << 4;     // B: 32 rows x 4 groups of 16

    // this thread's fixed cp.async destinations (byte addrs), per buffer
    uint32_t aDst[2], bDst[2];
#pragma unroll
    for (int b = 0; b < 2; b++) {
        aDst[b] = s2u(&sA[b][arow * 36 + ahalf]);
        bDst[b] = s2u(&sB[b][brow * 72 + boff]);
    }
    const float* aSrcBase = &Wm[(oB + arow) * C_ + ahalf];
    // B source row pointer depends on chunk: &X[(cc + brow) * N + nB + boff]

    float acc[2][4][4];
#pragma unroll
    for (int i = 0; i < 2; i++)
#pragma unroll
        for (int j = 0; j < 4; j++)
#pragma unroll
            for (int e = 0; e < 4; e++) acc[i][j][e] = 0.f;

    // stage chunk 0
#pragma unroll
    for (int gq = 0; gq < 4; gq++) {
        cp16(aDst[0] + 16 * gq, aSrcBase + 4 * gq);
        cp16(bDst[0] + 16 * gq, &X[brow * N + nB + boff + 4 * gq]);
    }
    CP_COMMIT();
    CP_WAIT0();
    __syncthreads();

    int buf = 0;
    for (int cc = 0; cc < C_; cc += 32) {
        bool pf = cc + 32 < C_;
        if (pf) {
            const float* aS = aSrcBase + cc + 32;
            const float* bS = &X[(cc + 32 + brow) * N + nB + boff];
#pragma unroll
            for (int gq = 0; gq < 4; gq++) {
                cp16(aDst[buf ^ 1] + 16 * gq, aS + 4 * gq);
                cp16(bDst[buf ^ 1] + 16 * gq, bS + 4 * gq);
            }
            CP_COMMIT();
        }
        const uint32_t* cA = sA[buf];
        const uint32_t* cB = sB[buf];
#pragma unroll
        for (int ks = 0; ks < 4; ks++) {
            int kb = ks << 3;
            uint32_t afr[2][4];
#pragma unroll
            for (int ms = 0; ms < 2; ms++) {
                int base = warp_m * 32 + ms * 16 + grp;
                afr[ms][0] = cA[(base    ) * 36 + kb + qd];
                afr[ms][1] = cA[(base + 8) * 36 + kb + qd];
                afr[ms][2] = cA[(base    ) * 36 + kb + 4 + qd];
                afr[ms][3] = cA[(base + 8) * 36 + kb + 4 + qd];
            }
            uint32_t bfr[4][2];
#pragma unroll
            for (int ns = 0; ns < 4; ns++) {
                int n = warp_n * 32 + ns * 8 + grp;
                bfr[ns][0] = cB[(kb + qd    ) * 72 + n];
                bfr[ns][1] = cB[(kb + 4 + qd) * 72 + n];
            }
#pragma unroll
            for (int ms = 0; ms < 2; ms++)
#pragma unroll
                for (int ns = 0; ns < 4; ns++)
                    mma_tf32(acc[ms][ns], afr[ms], bfr[ns]);
        }
        if (pf) CP_WAIT0();
        __syncthreads();
        buf ^= 1;
    }

    // epilogue
    if (!transp) {
#pragma unroll
        for (int ms = 0; ms < 2; ms++)
#pragma unroll
            for (int part = 0; part < 2; part++) {
                int row = warp_m * 32 + ms * 16 + grp + part * 8;
                float bv_ = bias[oB + row];
#pragma unroll
                for (int ns = 0; ns < 4; ns++) {
                    float2 val = make_float2(acc[ms][ns][2 * part] + bv_,
                                             acc[ms][ns][2 * part + 1] + bv_);
                    *(float2*)&Cout[(oB + row) * N + nB + warp_n * 32 + ns * 8 + 2 * qd] = val;
                }
            }
    } else {
        float* sT = (float*)smu;                 // [n][o], 64 x 65 = 4160 <= 9216
#pragma unroll
        for (int ms = 0; ms < 2; ms++)
#pragma unroll
            for (int part = 0; part < 2; part++) {
                int row = warp_m * 32 + ms * 16 + grp + part * 8;
                float bv_ = bias[oB + row];
#pragma unroll
                for (int ns = 0; ns < 4; ns++) {
                    int n = warp_n * 32 + ns * 8 + 2 * qd;
                    sT[(n    ) * 65 + row] = acc[ms][ns][2 * part] + bv_;
                    sT[(n + 1) * 65 + row] = acc[ms][ns][2 * part + 1] + bv_;
                }
            }
        __syncthreads();
#pragma unroll
        for (int it = 0; it < 32; it++) {
            int idx = it * 128 + tid;
            int n = idx >> 6, o = idx & 63;
            Cout[(nB + n) * C_ + oB + o] = sT[n * 65 + o];
        }
    }
}

// ---------------------------------------------------------------------------
// Kernel 3: fused attention via mma.sync tf32. Grid (18,8) = 144 CTAs x 256.
// (R8 verbatim — proven at ~9 us)
// ---------------------------------------------------------------------------
__global__ void __launch_bounds__(256) attn_kernel(const float* __restrict__ x,
                            const float* __restrict__ gamma_p,
                            float* __restrict__ out) {
    extern __shared__ float smd[];
    uint32_t* sQf = (uint32_t*)smd;        // 2048: A-frags [ms 2][ks 8][lane 32][4]
    float* sKV0 = smd + 2048;              // 64*68 = 4352 (tf32 bits)
    float* sKV1 = sKV0 + 4352;             // 4352
    float* sE   = sKV1 + 4352;             // 32*964 = 30848
    float* sInv = sE + 32 * SEW;           // 32

    int h   = blockIdx.y;
    int q0  = blockIdx.x * 32;
    int tid = threadIdx.x;
    int w = tid >> 5, lane = tid & 31, grp = lane >> 2, qd = lane & 3;
    int dstg = tid >> 2, cstg = (tid & 3) << 4;
    float* sKVb[2] = { sKV0, sKV1 };

    // ---- Stage Q fragments (one-time) ----
    {
        int q = tid >> 3, db = (tid & 7) << 3;
        float4 qa = *(const float4*)&g_QT[(q0 + q) * C_ + h * HD + db];
        float4 qb = *(const float4*)&g_QT[(q0 + q) * C_ + h * HD + db + 4];
        int ms = q >> 4, qg = q & 7, hi = (q >> 3) & 1;
        float qv[8] = {qa.x, qa.y, qa.z, qa.w, qb.x, qb.y, qb.z, qb.w};
#pragma unroll
        for (int e = 0; e < 8; e++) {
            int d = db + e;
            sQf[((ms * 8 + (d >> 3)) * 32 + (qg << 2) + (d & 3)) * 4 + hi + (((d >> 2) & 1) << 1)] = f2tf(qv[e]);
        }
    }
    // ---- preload K chunk 0 ----
    {
        const float4* src = (const float4*)&g_KT[dstg * C_ + h * HD + cstg];
        uint32_t* dst = (uint32_t*)&sKV0[dstg * 68 + cstg];
#pragma unroll
        for (int j = 0; j < 4; j++) {
            float4 r = src[j];
            *(uint4*)&dst[4 * j] = make_uint4(f2tf(r.x), f2tf(r.y), f2tf(r.z), f2tf(r.w));
        }
    }
    __syncthreads();

    // ---- Pass 1: E = Q^T K ----
    for (int kc = 0, c = 0; kc < KP; kc += 64, c++) {
        const uint32_t* cK = (const uint32_t*)sKVb[c & 1];
        bool pf = kc + 64 < KP;
        float4 r0, r1, r2, r3;
        if (pf) {
            const float4* src = (const float4*)&g_KT[(kc + 64 + dstg) * C_ + h * HD + cstg];
            r0 = src[0]; r1 = src[1]; r2 = src[2]; r3 = src[3];
        }
        float acc0[4] = {0.f, 0.f, 0.f, 0.f};
        float acc1[4] = {0.f, 0.f, 0.f, 0.f};
#pragma unroll
        for (int ks = 0; ks < 8; ks++) {
            uint4 a0 = *(const uint4*)&sQf[((    ks) * 32 + lane) * 4];
            uint4 a1 = *(const uint4*)&sQf[((8 + ks) * 32 + lane) * 4];
            uint32_t bf[2];
            bf[0] = cK[(w * 8 + grp) * 68 + ks * 8 + qd];
            bf[1] = cK[(w * 8 + grp) * 68 + ks * 8 + 4 + qd];
            mma_tf32(acc0, (const uint32_t*)&a0, bf);
            mma_tf32(acc1, (const uint32_t*)&a1, bf);
        }
        {
            int col = kc + w * 8 + 2 * qd;
            *(float2*)&sE[(grp     ) * SEW + col] = make_float2(acc0[0], acc0[1]);
            *(float2*)&sE[(grp +  8) * SEW + col] = make_float2(acc0[2], acc0[3]);
            *(float2*)&sE[(grp + 16) * SEW + col] = make_float2(acc1[0], acc1[1]);
            *(float2*)&sE[(grp + 24) * SEW + col] = make_float2(acc1[2], acc1[3]);
        }
        if (pf) {
            uint32_t* dst = (uint32_t*)&sKVb[(c & 1) ^ 1][dstg * 68 + cstg];
            *(uint4*)&dst[0]  = make_uint4(f2tf(r0.x), f2tf(r0.y), f2tf(r0.z), f2tf(r0.w));
            *(uint4*)&dst[4]  = make_uint4(f2tf(r1.x), f2tf(r1.y), f2tf(r1.z), f2tf(r1.w));
            *(uint4*)&dst[8]  = make_uint4(f2tf(r2.x), f2tf(r2.y), f2tf(r2.z), f2tf(r2.w));
            *(uint4*)&dst[12] = make_uint4(f2tf(r3.x), f2tf(r3.y), f2tf(r3.z), f2tf(r3.w));
        }
        __syncthreads();
    }

    // ---- prefetch V chunk 0 ----
    float4 v0r, v1r, v2r, v3r;
    {
        const float4* src = (const float4*)&g_V[(h * HD + dstg) * KP + cstg];
        v0r = src[0]; v1r = src[1]; v2r = src[2]; v3r = src[3];
    }

    // ---- Multiplicity-weighted softmax; tf32-rounded P in place ----
    {
        int row = tid >> 3, part = tid & 7;
        float* Er = &sE[row * SEW];
        int i0 = part * 120;
        float m = -1e30f;
        for (int i = i0; i < i0 + 120; i++) m = fmaxf(m, Er[i]);
        m = fmaxf(m, __shfl_xor_sync(~0u, m, 1));
        m = fmaxf(m, __shfl_xor_sync(~0u, m, 2));
        m = fmaxf(m, __shfl_xor_sync(~0u, m, 4));
        float s = 0.f;
        for (int i = i0; i < i0 + 120; i++) {
            float wgt = 0.f;
            if (i < PP) {
                int pr = i / PW, pc = i - pr * PW;
                int mr = min(pr + 1, min(7, PW - pr));
                int mc = min(pc + 1, min(7, PW - pc));
                wgt = (float)(mr * mc);
            }
            float p = __uint_as_float(f2tf(wgt * __expf(Er[i] - m)));
            Er[i] = p;
            s += p;
        }
        s += __shfl_xor_sync(~0u, s, 1);
        s += __shfl_xor_sync(~0u, s, 2);
        s += __shfl_xor_sync(~0u, s, 4);
        if (part == 0) sInv[row] = 1.f / s;
    }
    {
        uint32_t* dst = (uint32_t*)&sKV0[dstg * 68 + cstg];
        *(uint4*)&dst[0]  = make_uint4(f2tf(v0r.x), f2tf(v0r.y), f2tf(v0r.z), f2tf(v0r.w));
        *(uint4*)&dst[4]  = make_uint4(f2tf(v1r.x), f2tf(v1r.y), f2tf(v1r.z), f2tf(v1r.w));
        *(uint4*)&dst[8]  = make_uint4(f2tf(v2r.x), f2tf(v2r.y), f2tf(v2r.z), f2tf(v2r.w));
        *(uint4*)&dst[12] = make_uint4(f2tf(v3r.x), f2tf(v3r.y), f2tf(v3r.z), f2tf(v3r.w));
    }
    __syncthreads();

    // ---- Pass 2: out = P V ----
    float o0[4] = {0.f, 0.f, 0.f, 0.f};
    float o1[4] = {0.f, 0.f, 0.f, 0.f};
    for (int kc = 0, c = 0; kc < KP; kc += 64, c++) {
        const uint32_t* cV = (const uint32_t*)sKVb[c & 1];
        bool pf = kc + 64 < KP;
        float4 r0, r1, r2, r3;
        if (pf) {
            const float4* src = (const float4*)&g_V[(h * HD + dstg) * KP + kc + 64 + cstg];
            r0 = src[0]; r1 = src[1]; r2 = src[2]; r3 = src[3];
        }
#pragma unroll
        for (int ks = 0; ks < 8; ks++) {
            int colb = kc + ks * 8;
            uint32_t a0[4], a1[4], bf[2];
            a0[0] = __float_as_uint(sE[(grp     ) * SEW + colb + qd]);
            a0[1] = __float_as_uint(sE[(grp +  8) * SEW + colb + qd]);
            a0[2] = __float_as_uint(sE[(grp     ) * SEW + colb + 4 + qd]);
            a0[3] = __float_as_uint(sE[(grp +  8) * SEW + colb + 4 + qd]);
            a1[0] = __float_as_uint(sE[(grp + 16) * SEW + colb + qd]);
            a1[1] = __float_as_uint(sE[(grp + 24) * SEW + colb + qd]);
            a1[2] = __float_as_uint(sE[(grp + 16) * SEW + colb + 4 + qd]);
            a1[3] = __float_as_uint(sE[(grp + 24) * SEW + colb + 4 + qd]);
            bf[0] = cV[(w * 8 + grp) * 68 + ks * 8 + qd];
            bf[1] = cV[(w * 8 + grp) * 68 + ks * 8 + 4 + qd];
            mma_tf32(o0, a0, bf);
            mma_tf32(o1, a1, bf);
        }
        if (pf) {
            uint32_t* dst = (uint32_t*)&sKVb[(c & 1) ^ 1][dstg * 68 + cstg];
            *(uint4*)&dst[0]  = make_uint4(f2tf(r0.x), f2tf(r0.y), f2tf(r0.z), f2tf(r0.w));
            *(uint4*)&dst[4]  = make_uint4(f2tf(r1.x), f2tf(r1.y), f2tf(r1.z), f2tf(r1.w));
            *(uint4*)&dst[8]  = make_uint4(f2tf(r2.x), f2tf(r2.y), f2tf(r2.z), f2tf(r2.w));
            *(uint4*)&dst[12] = make_uint4(f2tf(r3.x), f2tf(r3.y), f2tf(r3.z), f2tf(r3.w));
        }
        __syncthreads();
    }

    // ---- Epilogue via smem transpose ----
    {
        float* sT = sKV0;                        // [d][q] 64 x 33 = 2112
        int dc = w * 8 + 2 * qd;
        sT[(dc    ) * 33 + grp     ] = o0[0];
        sT[(dc + 1) * 33 + grp     ] = o0[1];
        sT[(dc    ) * 33 + grp +  8] = o0[2];
        sT[(dc + 1) * 33 + grp +  8] = o0[3];
        sT[(dc    ) * 33 + grp + 16] = o1[0];
        sT[(dc + 1) * 33 + grp + 16] = o1[1];
        sT[(dc    ) * 33 + grp + 24] = o1[2];
        sT[(dc + 1) * 33 + grp + 24] = o1[3];
        __syncthreads();
        float g = *gamma_p;
        for (int i = tid; i < 64 * 32; i += 256) {
            int d = i >> 5, q = i & 31;
            int gi = (h * HD + d) * HW + q0 + q;
            out[gi] = g * sT[d * 33 + q] * sInv[q] + x[gi];
        }
    }
}

// ---------------------------------------------------------------------------
extern "C" void kernel_launch(void* const* d_in, const int* in_sizes, int n_in,
                              void* d_out, int out_size) {
    const float* x     = (const float*)d_in[0];
    const float* Wq    = (const float*)d_in[1];
    const float* bq    = (const float*)d_in[2];
    const float* Wk    = (const float*)d_in[3];
    const float* bk    = (const float*)d_in[4];
    const float* Wv    = (const float*)d_in[5];
    const float* bv    = (const float*)d_in[6];
    const float* gamma = (const float*)d_in[7];
    float* out = (float*)d_out;

    pad_kernel<<<(C_ * KP + 255) / 256, 256>>>(x);
    gemm_all_kernel<<<312, 128>>>(Wq, bq, Wk, bk, Wv, bv, x);

    const int attn_smem = (2048 + 2 * 4352 + 32 * SEW + 32) * 4;  // 166528
    cudaFuncSetAttribute(attn_kernel, cudaFuncAttributeMaxDynamicSharedMemorySize, attn_smem);
    attn_kernel<<<dim3(HW / 32, NH), 256, attn_smem>>>(x, gamma, out);
}

// round 13
// speedup vs baseline: 1.2773x; 1.0832x over previous
#include <cuda_runtime.h>
#include <cuda_bf16.h>
#include <cstdint>

#define C_  512
#define Hh  24
#define Ww  24
#define HW  576
#define NH  8
#define HD  64
#define PW  30
#define PP  900
#define KP  960
#define SEW 964            /* sE row stride: 4 mod 32 -> conflict-free frag reads */

typedef unsigned long long ull;

// Scratch (device globals: allocation-free)
__device__ float g_Xp[C_ * KP];   // reflect-padded x, keys padded to 960 (zeros)
__device__ float g_QT[HW * C_];   // Q transposed: [p][o]
__device__ float g_KT[KP * C_];   // K transposed: [pp][o]
__device__ float g_V [C_ * KP];   // V: [o][pp]

// ---- tf32 helpers (attention) ----
__device__ __forceinline__ uint32_t f2tf(float f) {
    uint32_t r; asm("cvt.rna.tf32.f32 %0, %1;" : "=r"(r) : "f"(f)); return r;
}
__device__ __forceinline__ void mma_tf32(float* c, const uint32_t* a, const uint32_t* b) {
    asm("mma.sync.aligned.m16n8k8.row.col.f32.tf32.tf32.f32 "
        "{%0,%1,%2,%3}, {%4,%5,%6,%7}, {%8,%9}, {%0,%1,%2,%3};"
        : "+f"(c[0]), "+f"(c[1]), "+f"(c[2]), "+f"(c[3])
        : "r"(a[0]), "r"(a[1]), "r"(a[2]), "r"(a[3]), "r"(b[0]), "r"(b[1]));
}

// ---- bf16 helpers (gemm) ----
__device__ __forceinline__ uint32_t pkbf(float lo, float hi) {
    __nv_bfloat162 h = __floats2bfloat162_rn(lo, hi);   // .x = lo (low 16 bits)
    return *(uint32_t*)&h;
}
__device__ __forceinline__ void mma_bf16(float* c, const uint32_t* a, const uint32_t* b) {
    asm("mma.sync.aligned.m16n8k16.row.col.f32.bf16.bf16.f32 "
        "{%0,%1,%2,%3}, {%4,%5,%6,%7}, {%8,%9}, {%0,%1,%2,%3};"
        : "+f"(c[0]), "+f"(c[1]), "+f"(c[2]), "+f"(c[3])
        : "r"(a[0]), "r"(a[1]), "r"(a[2]), "r"(a[3]), "r"(b[0]), "r"(b[1]));
}

// ---------------------------------------------------------------------------
// Kernel 1: reflect-pad gather. g_Xp[c][pp] (pp = pr*30+pc), zeros for pp>=900.
// ---------------------------------------------------------------------------
__global__ void pad_kernel(const float* __restrict__ x) {
    int idx = blockIdx.x * 256 + threadIdx.x;
    if (idx >= C_ * KP) return;
    int c = idx / KP, pp = idx - c * KP;
    float v = 0.f;
    if (pp < PP) {
        int pr = pp / PW, pc = pp - pr * PW;
        int r = pr - 3; r = (r < 0) ? -r : ((r >= Hh) ? 2 * Hh - 2 - r : r);
        int cl = pc - 3; cl = (cl < 0) ? -cl : ((cl >= Ww) ? 2 * Ww - 2 - cl : cl);
        v = x[c * HW + r * Ww + cl];
    }
    g_Xp[idx] = v;
}

// ---------------------------------------------------------------------------
// Kernel 2: three conv1x1 GEMMs via mma.sync BF16 m16n8k16.
// Halves mma count, fragment LDS, and operand smem vs the tf32 version.
// A smem [o][k2] packs (k,k+1) per u32; B smem [k2][n] packs two consecutive
// k-rows per u32 (vertical pair). Staging: register prefetch + fused bf16 pack.
//   bid [0,72)   : QT = (Wq @ x )^T (N=576, transposed store)
//   bid [72,192) : KT = (Wk @ Xp)^T (N=960, transposed store)
//   bid [192,312): V  =  Wv @ Xp    (N=960, direct store)
// CTA 64x64, 4 warps (2x2), warp tile 32x32. k-chunk 32 (2 x k16), dbl-buffer.
// ---------------------------------------------------------------------------
__global__ void __launch_bounds__(128) gemm_all_kernel(
    const float* __restrict__ Wq, const float* __restrict__ bq,
    const float* __restrict__ Wk, const float* __restrict__ bk,
    const float* __restrict__ Wv, const float* __restrict__ bv,
    const float* __restrict__ x)
{
    __shared__ uint32_t smu[4736];
    uint32_t* sA[2] = { smu,        smu + 1280 };   // [o=64][k2], stride 20
    uint32_t* sB[2] = { smu + 2560, smu + 3648 };   // [k2=16][n], stride 68

    int bid = blockIdx.x;
    const float *Wm, *bias, *X; float* Cout; int N, transp, nt, ot;
    if (bid < 72)       { nt = bid % 9;      ot = bid / 9;       Wm = Wq; bias = bq; X = x;    Cout = g_QT; N = HW; transp = 1; }
    else if (bid < 192) { int b = bid - 72;  nt = b % 15; ot = b / 15; Wm = Wk; bias = bk; X = g_Xp; Cout = g_KT; N = KP; transp = 1; }
    else                { int b = bid - 192; nt = b % 15; ot = b / 15; Wm = Wv; bias = bv; X = g_Xp; Cout = g_V;  N = KP; transp = 0; }
    int nB = nt * 64, oB = ot * 64;

    int tid  = threadIdx.x;
    int lane = tid & 31, wid = tid >> 5;
    int warp_m = wid & 1, warp_n = wid >> 1;     // 2x2 warps
    int grp = lane >> 2, qd = lane & 3;

    // staging maps
    int arow = tid >> 1, ahalf = tid & 1;        // A: 64 rows x 2 k-halves of 16 floats
    int bk2  = tid >> 3, bng = (tid & 7) << 3;   // B: 16 k2-rows x 8 n-groups of 8

    float acc[2][4][4];
#pragma unroll
    for (int i = 0; i < 2; i++)
#pragma unroll
        for (int j = 0; j < 4; j++)
#pragma unroll
            for (int e = 0; e < 4; e++) acc[i][j][e] = 0.f;

    // ---- stage chunk 0 ----
    {
        const float4* aS = (const float4*)&Wm[(oB + arow) * C_ + ahalf * 16];
        const float4* b0S = (const float4*)&X[(2 * bk2    ) * N + nB + bng];
        const float4* b1S = (const float4*)&X[(2 * bk2 + 1) * N + nB + bng];
        uint32_t aw[8], bw[8];
#pragma unroll
        for (int g = 0; g < 4; g++) {
            float4 w = aS[g];
            aw[2 * g]     = pkbf(w.x, w.y);
            aw[2 * g + 1] = pkbf(w.z, w.w);
        }
#pragma unroll
        for (int g = 0; g < 2; g++) {
            float4 lo = b0S[g], hi = b1S[g];
            bw[4 * g + 0] = pkbf(lo.x, hi.x);
            bw[4 * g + 1] = pkbf(lo.y, hi.y);
            bw[4 * g + 2] = pkbf(lo.z, hi.z);
            bw[4 * g + 3] = pkbf(lo.w, hi.w);
        }
        *(uint4*)&sA[0][arow * 20 + ahalf * 8]     = *(uint4*)&aw[0];
        *(uint4*)&sA[0][arow * 20 + ahalf * 8 + 4] = *(uint4*)&aw[4];
        *(uint4*)&sB[0][bk2 * 68 + bng]            = *(uint4*)&bw[0];
        *(uint4*)&sB[0][bk2 * 68 + bng + 4]        = *(uint4*)&bw[4];
    }
    __syncthreads();

    int buf = 0;
    for (int cc = 0; cc < C_; cc += 32) {
        bool pf = cc + 32 < C_;
        float4 wreg[4], x0reg[2], x1reg[2];
        if (pf) {
            const float4* aS = (const float4*)&Wm[(oB + arow) * C_ + cc + 32 + ahalf * 16];
            const float4* b0S = (const float4*)&X[(cc + 32 + 2 * bk2    ) * N + nB + bng];
            const float4* b1S = (const float4*)&X[(cc + 32 + 2 * bk2 + 1) * N + nB + bng];
#pragma unroll
            for (int g = 0; g < 4; g++) wreg[g] = aS[g];
            x0reg[0] = b0S[0]; x0reg[1] = b0S[1];
            x1reg[0] = b1S[0]; x1reg[1] = b1S[1];
        }
        const uint32_t* cA = sA[buf];
        const uint32_t* cB = sB[buf];
#pragma unroll
        for (int ks = 0; ks < 2; ks++) {            // two k16 steps per chunk
            int kb = ks << 3;
            uint32_t afr[2][4];
#pragma unroll
            for (int ms = 0; ms < 2; ms++) {
                int base = warp_m * 32 + ms * 16 + grp;
                afr[ms][0] = cA[(base    ) * 20 + kb + qd];
                afr[ms][1] = cA[(base + 8) * 20 + kb + qd];
                afr[ms][2] = cA[(base    ) * 20 + kb + 4 + qd];
                afr[ms][3] = cA[(base + 8) * 20 + kb + 4 + qd];
            }
            uint32_t bfr[4][2];
#pragma unroll
            for (int ns = 0; ns < 4; ns++) {
                int n = warp_n * 32 + ns * 8 + grp;
                bfr[ns][0] = cB[(kb + qd    ) * 68 + n];
                bfr[ns][1] = cB[(kb + 4 + qd) * 68 + n];
            }
#pragma unroll
            for (int ms = 0; ms < 2; ms++)
#pragma unroll
                for (int ns = 0; ns < 4; ns++)
                    mma_bf16(acc[ms][ns], afr[ms], bfr[ns]);
        }
        if (pf) {
            uint32_t* nA = sA[buf ^ 1];
            uint32_t* nBp = sB[buf ^ 1];
            uint32_t aw[8], bw[8];
#pragma unroll
            for (int g = 0; g < 4; g++) {
                aw[2 * g]     = pkbf(wreg[g].x, wreg[g].y);
                aw[2 * g + 1] = pkbf(wreg[g].z, wreg[g].w);
            }
#pragma unroll
            for (int g = 0; g < 2; g++) {
                float4 lo = x0reg[g], hi = x1reg[g];
                bw[4 * g + 0] = pkbf(lo.x, hi.x);
                bw[4 * g + 1] = pkbf(lo.y, hi.y);
                bw[4 * g + 2] = pkbf(lo.z, hi.z);
                bw[4 * g + 3] = pkbf(lo.w, hi.w);
            }
            *(uint4*)&nA[arow * 20 + ahalf * 8]     = *(uint4*)&aw[0];
            *(uint4*)&nA[arow * 20 + ahalf * 8 + 4] = *(uint4*)&aw[4];
            *(uint4*)&nBp[bk2 * 68 + bng]           = *(uint4*)&bw[0];
            *(uint4*)&nBp[bk2 * 68 + bng + 4]       = *(uint4*)&bw[4];
        }
        __syncthreads();
        buf ^= 1;
    }

    // ---- epilogue (same accumulator mapping as tf32 version) ----
    if (!transp) {
#pragma unroll
        for (int ms = 0; ms < 2; ms++)
#pragma unroll
            for (int part = 0; part < 2; part++) {
                int row = warp_m * 32 + ms * 16 + grp + part * 8;
                float bv_ = bias[oB + row];
#pragma unroll
                for (int ns = 0; ns < 4; ns++) {
                    float2 val = make_float2(acc[ms][ns][2 * part] + bv_,
                                             acc[ms][ns][2 * part + 1] + bv_);
                    *(float2*)&Cout[(oB + row) * N + nB + warp_n * 32 + ns * 8 + 2 * qd] = val;
                }
            }
    } else {
        float* sT = (float*)smu;                 // [n][o], 64 x 65 = 4160 <= 4736
        __syncthreads();                         // all frag reads of smu done
#pragma unroll
        for (int ms = 0; ms < 2; ms++)
#pragma unroll
            for (int part = 0; part < 2; part++) {
                int row = warp_m * 32 + ms * 16 + grp + part * 8;
                float bv_ = bias[oB + row];
#pragma unroll
                for (int ns = 0; ns < 4; ns++) {
                    int n = warp_n * 32 + ns * 8 + 2 * qd;
                    sT[(n    ) * 65 + row] = acc[ms][ns][2 * part] + bv_;
                    sT[(n + 1) * 65 + row] = acc[ms][ns][2 * part + 1] + bv_;
                }
            }
        __syncthreads();
#pragma unroll
        for (int it = 0; it < 32; it++) {
            int idx = it * 128 + tid;
            int n = idx >> 6, o = idx & 63;
            Cout[(nB + n) * C_ + oB + o] = sT[n * 65 + o];
        }
    }
}

// ---------------------------------------------------------------------------
// Kernel 3: fused attention via mma.sync tf32. Grid (18,8) = 144 CTAs x 256.
// (R8 verbatim — proven)
// ---------------------------------------------------------------------------
__global__ void __launch_bounds__(256) attn_kernel(const float* __restrict__ x,
                            const float* __restrict__ gamma_p,
                            float* __restrict__ out) {
    extern __shared__ float smd[];
    uint32_t* sQf = (uint32_t*)smd;        // 2048: A-frags [ms 2][ks 8][lane 32][4]
    float* sKV0 = smd + 2048;              // 64*68 = 4352 (tf32 bits)
    float* sKV1 = sKV0 + 4352;             // 4352
    float* sE   = sKV1 + 4352;             // 32*964 = 30848
    float* sInv = sE + 32 * SEW;           // 32

    int h   = blockIdx.y;
    int q0  = blockIdx.x * 32;
    int tid = threadIdx.x;
    int w = tid >> 5, lane = tid & 31, grp = lane >> 2, qd = lane & 3;
    int dstg = tid >> 2, cstg = (tid & 3) << 4;
    float* sKVb[2] = { sKV0, sKV1 };

    // ---- Stage Q fragments (one-time) ----
    {
        int q = tid >> 3, db = (tid & 7) << 3;
        float4 qa = *(const float4*)&g_QT[(q0 + q) * C_ + h * HD + db];
        float4 qb = *(const float4*)&g_QT[(q0 + q) * C_ + h * HD + db + 4];
        int ms = q >> 4, qg = q & 7, hi = (q >> 3) & 1;
        float qv[8] = {qa.x, qa.y, qa.z, qa.w, qb.x, qb.y, qb.z, qb.w};
#pragma unroll
        for (int e = 0; e < 8; e++) {
            int d = db + e;
            sQf[((ms * 8 + (d >> 3)) * 32 + (qg << 2) + (d & 3)) * 4 + hi + (((d >> 2) & 1) << 1)] = f2tf(qv[e]);
        }
    }
    // ---- preload K chunk 0 ----
    {
        const float4* src = (const float4*)&g_KT[dstg * C_ + h * HD + cstg];
        uint32_t* dst = (uint32_t*)&sKV0[dstg * 68 + cstg];
#pragma unroll
        for (int j = 0; j < 4; j++) {
            float4 r = src[j];
            *(uint4*)&dst[4 * j] = make_uint4(f2tf(r.x), f2tf(r.y), f2tf(r.z), f2tf(r.w));
        }
    }
    __syncthreads();

    // ---- Pass 1: E = Q^T K ----
    for (int kc = 0, c = 0; kc < KP; kc += 64, c++) {
        const uint32_t* cK = (const uint32_t*)sKVb[c & 1];
        bool pf = kc + 64 < KP;
        float4 r0, r1, r2, r3;
        if (pf) {
            const float4* src = (const float4*)&g_KT[(kc + 64 + dstg) * C_ + h * HD + cstg];
            r0 = src[0]; r1 = src[1]; r2 = src[2]; r3 = src[3];
        }
        float acc0[4] = {0.f, 0.f, 0.f, 0.f};
        float acc1[4] = {0.f, 0.f, 0.f, 0.f};
#pragma unroll
        for (int ks = 0; ks < 8; ks++) {
            uint4 a0 = *(const uint4*)&sQf[((    ks) * 32 + lane) * 4];
            uint4 a1 = *(const uint4*)&sQf[((8 + ks) * 32 + lane) * 4];
            uint32_t bf[2];
            bf[0] = cK[(w * 8 + grp) * 68 + ks * 8 + qd];
            bf[1] = cK[(w * 8 + grp) * 68 + ks * 8 + 4 + qd];
            mma_tf32(acc0, (const uint32_t*)&a0, bf);
            mma_tf32(acc1, (const uint32_t*)&a1, bf);
        }
        {
            int col = kc + w * 8 + 2 * qd;
            *(float2*)&sE[(grp     ) * SEW + col] = make_float2(acc0[0], acc0[1]);
            *(float2*)&sE[(grp +  8) * SEW + col] = make_float2(acc0[2], acc0[3]);
            *(float2*)&sE[(grp + 16) * SEW + col] = make_float2(acc1[0], acc1[1]);
            *(float2*)&sE[(grp + 24) * SEW + col] = make_float2(acc1[2], acc1[3]);
        }
        if (pf) {
            uint32_t* dst = (uint32_t*)&sKVb[(c & 1) ^ 1][dstg * 68 + cstg];
            *(uint4*)&dst[0]  = make_uint4(f2tf(r0.x), f2tf(r0.y), f2tf(r0.z), f2tf(r0.w));
            *(uint4*)&dst[4]  = make_uint4(f2tf(r1.x), f2tf(r1.y), f2tf(r1.z), f2tf(r1.w));
            *(uint4*)&dst[8]  = make_uint4(f2tf(r2.x), f2tf(r2.y), f2tf(r2.z), f2tf(r2.w));
            *(uint4*)&dst[12] = make_uint4(f2tf(r3.x), f2tf(r3.y), f2tf(r3.z), f2tf(r3.w));
        }
        __syncthreads();
    }

    // ---- prefetch V chunk 0 ----
    float4 v0r, v1r, v2r, v3r;
    {
        const float4* src = (const float4*)&g_V[(h * HD + dstg) * KP + cstg];
        v0r = src[0]; v1r = src[1]; v2r = src[2]; v3r = src[3];
    }

    // ---- Multiplicity-weighted softmax; tf32-rounded P in place ----
    {
        int row = tid >> 3, part = tid & 7;
        float* Er = &sE[row * SEW];
        int i0 = part * 120;
        float m = -1e30f;
        for (int i = i0; i < i0 + 120; i++) m = fmaxf(m, Er[i]);
        m = fmaxf(m, __shfl_xor_sync(~0u, m, 1));
        m = fmaxf(m, __shfl_xor_sync(~0u, m, 2));
        m = fmaxf(m, __shfl_xor_sync(~0u, m, 4));
        float s = 0.f;
        for (int i = i0; i < i0 + 120; i++) {
            float wgt = 0.f;
            if (i < PP) {
                int pr = i / PW, pc = i - pr * PW;
                int mr = min(pr + 1, min(7, PW - pr));
                int mc = min(pc + 1, min(7, PW - pc));
                wgt = (float)(mr * mc);
            }
            float p = __uint_as_float(f2tf(wgt * __expf(Er[i] - m)));
            Er[i] = p;
            s += p;
        }
        s += __shfl_xor_sync(~0u, s, 1);
        s += __shfl_xor_sync(~0u, s, 2);
        s += __shfl_xor_sync(~0u, s, 4);
        if (part == 0) sInv[row] = 1.f / s;
    }
    {
        uint32_t* dst = (uint32_t*)&sKV0[dstg * 68 + cstg];
        *(uint4*)&dst[0]  = make_uint4(f2tf(v0r.x), f2tf(v0r.y), f2tf(v0r.z), f2tf(v0r.w));
        *(uint4*)&dst[4]  = make_uint4(f2tf(v1r.x), f2tf(v1r.y), f2tf(v1r.z), f2tf(v1r.w));
        *(uint4*)&dst[8]  = make_uint4(f2tf(v2r.x), f2tf(v2r.y), f2tf(v2r.z), f2tf(v2r.w));
        *(uint4*)&dst[12] = make_uint4(f2tf(v3r.x), f2tf(v3r.y), f2tf(v3r.z), f2tf(v3r.w));
    }
    __syncthreads();

    // ---- Pass 2: out = P V ----
    float o0[4] = {0.f, 0.f, 0.f, 0.f};
    float o1[4] = {0.f, 0.f, 0.f, 0.f};
    for (int kc = 0, c = 0; kc < KP; kc += 64, c++) {
        const uint32_t* cV = (const uint32_t*)sKVb[c & 1];
        bool pf = kc + 64 < KP;
        float4 r0, r1, r2, r3;
        if (pf) {
            const float4* src = (const float4*)&g_V[(h * HD + dstg) * KP + kc + 64 + cstg];
            r0 = src[0]; r1 = src[1]; r2 = src[2]; r3 = src[3];
        }
#pragma unroll
        for (int ks = 0; ks < 8; ks++) {
            int colb = kc + ks * 8;
            uint32_t a0[4], a1[4], bf[2];
            a0[0] = __float_as_uint(sE[(grp     ) * SEW + colb + qd]);
            a0[1] = __float_as_uint(sE[(grp +  8) * SEW + colb + qd]);
            a0[2] = __float_as_uint(sE[(grp     ) * SEW + colb + 4 + qd]);
            a0[3] = __float_as_uint(sE[(grp +  8) * SEW + colb + 4 + qd]);
            a1[0] = __float_as_uint(sE[(grp + 16) * SEW + colb + qd]);
            a1[1] = __float_as_uint(sE[(grp + 24) * SEW + colb + qd]);
            a1[2] = __float_as_uint(sE[(grp + 16) * SEW + colb + 4 + qd]);
            a1[3] = __float_as_uint(sE[(grp + 24) * SEW + colb + 4 + qd]);
            bf[0] = cV[(w * 8 + grp) * 68 + ks * 8 + qd];
            bf[1] = cV[(w * 8 + grp) * 68 + ks * 8 + 4 + qd];
            mma_tf32(o0, a0, bf);
            mma_tf32(o1, a1, bf);
        }
        if (pf) {
            uint32_t* dst = (uint32_t*)&sKVb[(c & 1) ^ 1][dstg * 68 + cstg];
            *(uint4*)&dst[0]  = make_uint4(f2tf(r0.x), f2tf(r0.y), f2tf(r0.z), f2tf(r0.w));
            *(uint4*)&dst[4]  = make_uint4(f2tf(r1.x), f2tf(r1.y), f2tf(r1.z), f2tf(r1.w));
            *(uint4*)&dst[8]  = make_uint4(f2tf(r2.x), f2tf(r2.y), f2tf(r2.z), f2tf(r2.w));
            *(uint4*)&dst[12] = make_uint4(f2tf(r3.x), f2tf(r3.y), f2tf(r3.z), f2tf(r3.w));
        }
        __syncthreads();
    }

    // ---- Epilogue via smem transpose ----
    {
        float* sT = sKV0;                        // [d][q] 64 x 33 = 2112
        int dc = w * 8 + 2 * qd;
        sT[(dc    ) * 33 + grp     ] = o0[0];
        sT[(dc + 1) * 33 + grp     ] = o0[1];
        sT[(dc    ) * 33 + grp +  8] = o0[2];
        sT[(dc + 1) * 33 + grp +  8] = o0[3];
        sT[(dc    ) * 33 + grp + 16] = o1[0];
        sT[(dc + 1) * 33 + grp + 16] = o1[1];
        sT[(dc    ) * 33 + grp + 24] = o1[2];
        sT[(dc + 1) * 33 + grp + 24] = o1[3];
        __syncthreads();
        float g = *gamma_p;
        for (int i = tid; i < 64 * 32; i += 256) {
            int d = i >> 5, q = i & 31;
            int gi = (h * HD + d) * HW + q0 + q;
            out[gi] = g * sT[d * 33 + q] * sInv[q] + x[gi];
        }
    }
}

// ---------------------------------------------------------------------------
extern "C" void kernel_launch(void* const* d_in, const int* in_sizes, int n_in,
                              void* d_out, int out_size) {
    const float* x     = (const float*)d_in[0];
    const float* Wq    = (const float*)d_in[1];
    const float* bq    = (const float*)d_in[2];
    const float* Wk    = (const float*)d_in[3];
    const float* bk    = (const float*)d_in[4];
    const float* Wv    = (const float*)d_in[5];
    const float* bv    = (const float*)d_in[6];
    const float* gamma = (const float*)d_in[7];
    float* out = (float*)d_out;

    pad_kernel<<<(C_ * KP + 255) / 256, 256>>>(x);
    gemm_all_kernel<<<312, 128>>>(Wq, bq, Wk, bk, Wv, bv, x);

    const int attn_smem = (2048 + 2 * 4352 + 32 * SEW + 32) * 4;  // 166528
    cudaFuncSetAttribute(attn_kernel, cudaFuncAttributeMaxDynamicSharedMemorySize, attn_smem);
    attn_kernel<<<dim3(HW / 32, NH), 256, attn_smem>>>(x, gamma, out);
}